// round 15
// baseline (speedup 1.0000x reference)
#include <cuda_runtime.h>
#include <cuda_fp16.h>
#include <math.h>
#include <stdint.h>

// Problem constants
#define BB 2
#define SS 2048
#define DD 1024
#define HH 16
#define KVH 4
#define HDIM 64
#define NREP (HH / KVH)   // 4

// Scratch (allocation-free: __device__ globals)
__device__ __half g_qt[BB * HH * SS * HDIM];    // roped Q fp16, FSC folded
__device__ __half g_kt[BB * KVH * SS * HDIM];   // roped K fp16
__device__ __half g_vh[BB * SS * KVH * HDIM];   // V fp16 (b,s,kv,d)
__device__ __half g_vtT[BB * KVH * HDIM * SS];  // V^T fp16: [b][kv][d][s]
__device__ __half g_attn[BB * SS * HH * HDIM];  // attention out, fp16
__device__ __half g_xh[BB * SS * DD];           // x fp16 [M][K]
__device__ __half g_wqt[DD * DD];               // Wq^T fp16 [N][K]
__device__ __half g_wkt[256 * DD];
__device__ __half g_wvt[256 * DD];
__device__ __half g_wot[DD * DD];

#define FSC 0.18033688011112042f   // 0.125 * log2(e)

__device__ __forceinline__ float ex2(float x) {
    float y;
    asm("ex2.approx.ftz.f32 %0, %1;" : "=f"(y) : "f"(x));
    return y;
}
__device__ __forceinline__ void mma_f16(float d[4], const uint32_t a[4],
                                        const uint32_t b[2], const float c[4]) {
    asm volatile(
        "mma.sync.aligned.m16n8k16.row.col.f32.f16.f16.f32 "
        "{%0,%1,%2,%3}, {%4,%5,%6,%7}, {%8,%9}, {%10,%11,%12,%13};"
        : "=f"(d[0]), "=f"(d[1]), "=f"(d[2]), "=f"(d[3])
        : "r"(a[0]), "r"(a[1]), "r"(a[2]), "r"(a[3]),
          "r"(b[0]), "r"(b[1]),
          "f"(c[0]), "f"(c[1]), "f"(c[2]), "f"(c[3]));
}
__device__ __forceinline__ void ldsm_x4(uint32_t& r0, uint32_t& r1,
                                        uint32_t& r2, uint32_t& r3, uint32_t addr) {
    asm volatile("ldmatrix.sync.aligned.m8n8.x4.shared.b16 {%0,%1,%2,%3}, [%4];"
                 : "=r"(r0), "=r"(r1), "=r"(r2), "=r"(r3) : "r"(addr));
}
__device__ __forceinline__ void cpa16(uint32_t dst, const void* src) {
    asm volatile("cp.async.ca.shared.global [%0], [%1], 16;"
                 :: "r"(dst), "l"(src));
}
__device__ __forceinline__ void cp_commit() {
    asm volatile("cp.async.commit_group;" ::: "memory");
}
template <int N>
__device__ __forceinline__ void cp_wait() {
    asm volatile("cp.async.wait_group %0;" :: "n"(N) : "memory");
}

// ---------------------------------------------------------------------------
// Merged prep: one launch converts x -> fp16 AND all four W -> fp16 [N][K].
// blocks [0,2560): W transpose tiles; [2560, 6656): x conversion.
// ---------------------------------------------------------------------------
__global__ void prep_all_kernel(const float* __restrict__ x,
                                const float* __restrict__ Wq,
                                const float* __restrict__ Wk,
                                const float* __restrict__ Wv,
                                const float* __restrict__ Wo,
                                __half* __restrict__ xh,
                                __half* __restrict__ wqt,
                                __half* __restrict__ wkt,
                                __half* __restrict__ wvt,
                                __half* __restrict__ wot)
{
    const int tid = threadIdx.x;
    int bid = blockIdx.x;
    if (bid >= 2560) {
        // x conversion: float4 index
        int i = (bid - 2560) * 256 + tid;
        float4 v = ((const float4*)x)[i];
        __half2* o = (__half2*)xh;
        o[2 * i]     = __floats2half2_rn(v.x, v.y);
        o[2 * i + 1] = __floats2half2_rn(v.z, v.w);
        return;
    }
    __shared__ float tile[32][33];
    const float* W;
    __half* Wt;
    int N, n_t, k_t;
    if (bid < 1024)      { W = Wq; Wt = wqt; N = 1024; n_t = bid & 31; k_t = bid >> 5; }
    else if (bid < 1280) { W = Wk; Wt = wkt; N = 256;  bid -= 1024; n_t = bid & 7; k_t = bid >> 3; }
    else if (bid < 1536) { W = Wv; Wt = wvt; N = 256;  bid -= 1280; n_t = bid & 7; k_t = bid >> 3; }
    else                 { W = Wo; Wt = wot; N = 1024; bid -= 1536; n_t = bid & 31; k_t = bid >> 5; }
    const int n0 = n_t * 32, k0 = k_t * 32;
    const int tx = tid & 31;
    const int ty0 = tid >> 5;
#pragma unroll
    for (int ty = ty0; ty < 32; ty += 8)
        tile[ty][tx] = W[(size_t)(k0 + ty) * N + n0 + tx];
    __syncthreads();
#pragma unroll
    for (int ty = ty0; ty < 32; ty += 8)
        Wt[(size_t)(n0 + ty) * DD + k0 + tx] = __float2half_rn(tile[tx][ty]);
}

// ---------------------------------------------------------------------------
// fp16 ldmatrix GEMM, 3-stage cp.async pipeline, ONE barrier per k-tile.
// CTA 128x128, 128 threads (4 warps 2x2), warp tile 64x64, BK=64, SW128.
// ---------------------------------------------------------------------------
#define XTILE_B 16384
#define XSTAGE_B (XTILE_B * 2)
#define XSTAGES 3
#define XGSMEM (XSTAGE_B * XSTAGES)   // 96 KB

__device__ __forceinline__ void xgemm_copy_tile(
    const __half* __restrict__ A, const __half* __restrict__ Bt,
    int K, int bm, int bn, int k0,
    uint32_t abase, uint32_t bbase, int tid)
{
#pragma unroll
    for (int i = 0; i < 8; i++) {
        int e = tid + i * 128;
        int row = e >> 3;
        int ch = e & 7;
        int sch = ch ^ (row & 7);
        cpa16(abase + row * 128 + sch * 16,
              A + (size_t)(bm + row) * K + k0 + ch * 8);
    }
#pragma unroll
    for (int i = 0; i < 8; i++) {
        int e = tid + i * 128;
        int row = e >> 3;
        int ch = e & 7;
        int sch = ch ^ (row & 7);
        cpa16(bbase + row * 128 + sch * 16,
              Bt + (size_t)(bn + row) * K + k0 + ch * 8);
    }
}

__device__ __forceinline__ void xgemm_compute_tile(
    uint32_t abase, uint32_t bbase, float acc[4][8][4],
    int warpM, int warpN, int lane)
{
    const int lrow = lane & 15;
    const int lhi = lane >> 4;
#pragma unroll
    for (int ki = 0; ki < 4; ki++) {
        uint32_t av[4][4];
        uint32_t bv[4][4];
#pragma unroll
        for (int mi = 0; mi < 4; mi++) {
            int row = warpM + mi * 16 + lrow;
            int ch = (ki * 2 + lhi) ^ (row & 7);
            ldsm_x4(av[mi][0], av[mi][1], av[mi][2], av[mi][3],
                    abase + row * 128 + ch * 16);
        }
#pragma unroll
        for (int nj = 0; nj < 4; nj++) {
            int row = warpN + nj * 16 + lrow;
            int ch = (ki * 2 + lhi) ^ (row & 7);
            ldsm_x4(bv[nj][0], bv[nj][1], bv[nj][2], bv[nj][3],
                    bbase + row * 128 + ch * 16);
        }
#pragma unroll
        for (int mi = 0; mi < 4; mi++)
#pragma unroll
            for (int nt = 0; nt < 8; nt++) {
                uint32_t b[2];
                b[0] = bv[nt >> 1][nt & 1];
                b[1] = bv[nt >> 1][2 + (nt & 1)];
                mma_f16(acc[mi][nt], av[mi], b, acc[mi][nt]);
            }
    }
}

__device__ __forceinline__ void xgemm_mainloop(
    const __half* __restrict__ A, const __half* __restrict__ Bt,
    int K, int bm, int bn, float acc[4][8][4],
    int warpM, int warpN, int tid, int lane)
{
    extern __shared__ __align__(16) char xsm[];
    const uint32_t s0 = (uint32_t)__cvta_generic_to_shared(xsm);

#pragma unroll
    for (int mi = 0; mi < 4; mi++)
#pragma unroll
        for (int nt = 0; nt < 8; nt++)
#pragma unroll
            for (int e = 0; e < 4; e++) acc[mi][nt][e] = 0.f;

    const int T = K / 64;   // >= 2

    // Prologue: issue tiles 0 and 1
    xgemm_copy_tile(A, Bt, K, bm, bn, 0, s0, s0 + XTILE_B, tid);
    cp_commit();
    xgemm_copy_tile(A, Bt, K, bm, bn, 64,
                    s0 + XSTAGE_B, s0 + XSTAGE_B + XTILE_B, tid);
    cp_commit();

    int stg = 0;          // stage of tile t
    for (int t = 0; t < T; t++) {
        cp_wait<1>();     // tile t has landed
        __syncthreads();  // single barrier per tile: also guards stage reuse
        if (t + 2 < T) {
            int ns = stg + 2;
            if (ns >= XSTAGES) ns -= XSTAGES;
            uint32_t base = s0 + ns * XSTAGE_B;
            xgemm_copy_tile(A, Bt, K, bm, bn, (t + 2) * 64,
                            base, base + XTILE_B, tid);
            cp_commit();
        }
        uint32_t base = s0 + stg * XSTAGE_B;
        xgemm_compute_tile(base, base + XTILE_B, acc, warpM, warpN, lane);
        if (++stg == XSTAGES) stg = 0;
    }
}

// ---------------------------------------------------------------------------
// Fused QKV projection with RoPE epilogue
// ---------------------------------------------------------------------------
__global__ __launch_bounds__(128)
void gemm_qkv_kernel(const __half* __restrict__ xh,
                     const __half* __restrict__ Wqt,
                     const __half* __restrict__ Wkt,
                     const __half* __restrict__ Wvt,
                     const float* __restrict__ cosT,
                     const float* __restrict__ sinT,
                     __half* __restrict__ qt,
                     __half* __restrict__ kt,
                     __half* __restrict__ vh)
{
    const int tid = threadIdx.x;
    const int lane = tid & 31;
    const int warp = tid >> 5;
    const int q = lane >> 2;
    const int r = lane & 3;
    const int warpM = (warp >> 1) * 64;
    const int warpN = (warp & 1) * 64;

    const int bx = blockIdx.x;
    const int bm = blockIdx.y * 128;

    const __half* Bt;
    int bn;
    if (bx < 8)       { Bt = Wqt; bn = bx * 128; }
    else if (bx < 10) { Bt = Wkt; bn = (bx - 8) * 128; }
    else              { Bt = Wvt; bn = (bx - 10) * 128; }

    float acc[4][8][4];
    xgemm_mainloop(xh, Bt, DD, bm, bn, acc, warpM, warpN, tid, lane);

    if (bx < 10) {
        const bool isQ = (bx < 8);
        const int head = (bn + warpN) >> 6;
        const float fs = isQ ? FSC : 1.0f;
#pragma unroll
        for (int mi = 0; mi < 4; mi++) {
            int rg0 = bm + warpM + mi * 16 + q;
#pragma unroll
            for (int hv = 0; hv < 2; hv++) {
                int rg = rg0 + hv * 8;
                int bb = rg >> 11;
                int s = rg & 2047;
                const float* crow = cosT + s * HDIM;
                const float* srow = sinT + s * HDIM;
                __half* orow;
                if (isQ)
                    orow = qt + (((size_t)(bb * HH + head) * SS + s) << 6);
                else
                    orow = kt + (((size_t)(bb * KVH + head) * SS + s) << 6);
#pragma unroll
                for (int nt = 0; nt < 4; nt++) {
                    int d = nt * 8 + 2 * r;
                    float2 cl = *(const float2*)(crow + d);
                    float2 sl = *(const float2*)(srow + d);
                    float2 chg = *(const float2*)(crow + d + 32);
                    float2 shg = *(const float2*)(srow + d + 32);
                    float v0 = acc[mi][nt][2 * hv];
                    float v1 = acc[mi][nt][2 * hv + 1];
                    float w0 = acc[mi][nt + 4][2 * hv];
                    float w1 = acc[mi][nt + 4][2 * hv + 1];
                    float lo0 = (v0 * cl.x - w0 * sl.x) * fs;
                    float lo1 = (v1 * cl.y - w1 * sl.y) * fs;
                    float hi0 = (w0 * chg.x + v0 * shg.x) * fs;
                    float hi1 = (w1 * chg.y + v1 * shg.y) * fs;
                    *(__half2*)(orow + d) = __floats2half2_rn(lo0, lo1);
                    *(__half2*)(orow + d + 32) = __floats2half2_rn(hi0, hi1);
                }
            }
        }
    } else {
#pragma unroll
        for (int mi = 0; mi < 4; mi++) {
            int rg0 = bm + warpM + mi * 16 + q;
#pragma unroll
            for (int nt = 0; nt < 8; nt++) {
                int col = bn + warpN + nt * 8 + 2 * r;
                *(__half2*)(vh + (size_t)rg0 * 256 + col) =
                    __floats2half2_rn(acc[mi][nt][0], acc[mi][nt][1]);
                *(__half2*)(vh + (size_t)(rg0 + 8) * 256 + col) =
                    __floats2half2_rn(acc[mi][nt][2], acc[mi][nt][3]);
            }
        }
    }
}

__global__ __launch_bounds__(128)
void gemm_o_kernel(const __half* __restrict__ A, const __half* __restrict__ Bt,
                   float* __restrict__ C)
{
    const int tid = threadIdx.x;
    const int lane = tid & 31;
    const int warp = tid >> 5;
    const int q = lane >> 2;
    const int r = lane & 3;
    const int warpM = (warp >> 1) * 64;
    const int warpN = (warp & 1) * 64;
    const int bm = blockIdx.y * 128;
    const int bn = blockIdx.x * 128;

    float acc[4][8][4];
    xgemm_mainloop(A, Bt, DD, bm, bn, acc, warpM, warpN, tid, lane);

#pragma unroll
    for (int mi = 0; mi < 4; mi++) {
        int row0 = bm + warpM + mi * 16 + q;
#pragma unroll
        for (int nt = 0; nt < 8; nt++) {
            int col = bn + warpN + nt * 8 + 2 * r;
            *(float2*)(C + (size_t)row0 * DD + col) =
                make_float2(acc[mi][nt][0], acc[mi][nt][1]);
            *(float2*)(C + (size_t)(row0 + 8) * DD + col) =
                make_float2(acc[mi][nt][2], acc[mi][nt][3]);
        }
    }
}

// ---------------------------------------------------------------------------
// V transpose: vh (b,s,kv,d) fp16 -> vtT (b,kv,d,s) fp16
// ---------------------------------------------------------------------------
__global__ void vtrans_kernel(const __half* __restrict__ vh,
                              __half* __restrict__ vtT)
{
    __shared__ __half tile[32][33];
    const int s0 = blockIdx.x * 32;
    const int d0 = (blockIdx.y & 1) * 32;
    const int bkv = blockIdx.y >> 1;
    const int b = bkv >> 2;
    const int kv = bkv & 3;
    const int tx = threadIdx.x;
#pragma unroll
    for (int ty = threadIdx.y; ty < 32; ty += 8)
        tile[ty][tx] = vh[(((size_t)(b * SS + s0 + ty)) * KVH + kv) * HDIM + d0 + tx];
    __syncthreads();
#pragma unroll
    for (int ty = threadIdx.y; ty < 32; ty += 8)
        vtT[((size_t)bkv * HDIM + d0 + ty) * SS + s0 + tx] = tile[tx][ty];
}

// ---------------------------------------------------------------------------
// fp16 MMA flash attention (R11 design — best performer: 64q/CTA, 4 warps)
// ---------------------------------------------------------------------------
#define HS 72
#define HSW 36

__global__ __launch_bounds__(128)
void flash_mma_kernel(const __half* __restrict__ Qt, const __half* __restrict__ Kt,
                      const __half* __restrict__ VtT, __half* __restrict__ attn)
{
    __shared__ __align__(16) __half Ks[64 * HS];
    __shared__ __align__(16) __half Vs[64 * HS];
    __shared__ __align__(16) __half Ps[64 * HS];

    const int tid = threadIdx.x;
    const int lane = tid & 31;
    const int w = tid >> 5;
    const int q = lane >> 2;
    const int r = lane & 3;

    const int bx = gridDim.x - 1 - blockIdx.x;
    const int bh = blockIdx.y;
    const int b = bh >> 4;
    const int h = bh & 15;
    const int kvh = h >> 2;

    const __half* qbase = Qt + ((size_t)bh * SS + bx * 64) * HDIM;
    const __half* kbase = Kt + (size_t)(b * KVH + kvh) * SS * HDIM;
    const __half* vbase = VtT + (size_t)(b * KVH + kvh) * HDIM * SS;

#pragma unroll
    for (int it = 0; it < 4; it++) {
        int e = tid + it * 128;
        int row = e >> 3;
        int ch = e & 7;
        *(uint4*)(Ps + row * HS + ch * 8) =
            *(const uint4*)(qbase + row * HDIM + ch * 8);
    }
    __syncthreads();

    uint32_t qf[4][4];
    {
        const uint32_t* Pw = (const uint32_t*)Ps;
#pragma unroll
        for (int ki = 0; ki < 4; ki++) {
            const uint32_t* p = Pw + (w * 16 + q) * HSW + ki * 8 + r;
            qf[ki][0] = p[0];
            qf[ki][1] = p[8 * HSW];
            qf[ki][2] = p[4];
            qf[ki][3] = p[8 * HSW + 4];
        }
    }
    __syncthreads();

    float of[8][4];
#pragma unroll
    for (int nt = 0; nt < 8; nt++)
#pragma unroll
        for (int e = 0; e < 4; e++) of[nt][e] = 0.f;
    float m0 = -INFINITY, m1 = -INFINITY, l0 = 0.f, l1 = 0.f;

    for (int jt = 0; jt <= bx; jt++) {
        __syncthreads();
#pragma unroll
        for (int it = 0; it < 4; it++) {
            int e = tid + it * 128;
            int row = e >> 3;
            int ch = e & 7;
            *(uint4*)(Ks + row * HS + ch * 8) =
                *(const uint4*)(kbase + (size_t)(jt * 64 + row) * HDIM + ch * 8);
            *(uint4*)(Vs + row * HS + ch * 8) =
                *(const uint4*)(vbase + (size_t)row * SS + jt * 64 + ch * 8);
        }
        __syncthreads();

        float sf[8][4];
#pragma unroll
        for (int nt = 0; nt < 8; nt++)
#pragma unroll
            for (int e = 0; e < 4; e++) sf[nt][e] = 0.f;
        {
            const uint32_t* Kw = (const uint32_t*)Ks;
#pragma unroll
            for (int ki = 0; ki < 4; ki++) {
#pragma unroll
                for (int nt = 0; nt < 8; nt++) {
                    uint32_t bfr[2];
                    const uint32_t* kp = Kw + (nt * 8 + q) * HSW + ki * 8 + r;
                    bfr[0] = kp[0];
                    bfr[1] = kp[4];
                    mma_f16(sf[nt], qf[ki], bfr, sf[nt]);
                }
            }
        }

        if (jt == bx) {
            const int rowA = w * 16 + q;
            const int rowB = rowA + 8;
#pragma unroll
            for (int nt = 0; nt < 8; nt++) {
                int col = nt * 8 + 2 * r;
                if (col     > rowA) sf[nt][0] = -1e30f;
                if (col + 1 > rowA) sf[nt][1] = -1e30f;
                if (col     > rowB) sf[nt][2] = -1e30f;
                if (col + 1 > rowB) sf[nt][3] = -1e30f;
            }
        }

        float mxA = -1e30f, mxB = -1e30f;
#pragma unroll
        for (int nt = 0; nt < 8; nt++) {
            mxA = fmaxf(mxA, fmaxf(sf[nt][0], sf[nt][1]));
            mxB = fmaxf(mxB, fmaxf(sf[nt][2], sf[nt][3]));
        }
        mxA = fmaxf(mxA, __shfl_xor_sync(0xffffffffu, mxA, 1));
        mxA = fmaxf(mxA, __shfl_xor_sync(0xffffffffu, mxA, 2));
        mxB = fmaxf(mxB, __shfl_xor_sync(0xffffffffu, mxB, 1));
        mxB = fmaxf(mxB, __shfl_xor_sync(0xffffffffu, mxB, 2));

        float mn0 = fmaxf(m0, mxA);
        float mn1 = fmaxf(m1, mxB);
        float sc0 = ex2(m0 - mn0);
        float sc1 = ex2(m1 - mn1);
        m0 = mn0; m1 = mn1;

        float rs0 = 0.f, rs1 = 0.f;
        __half* prow = Ps + (w * 16 + q) * HS;
#pragma unroll
        for (int nt = 0; nt < 8; nt++) {
            float p00 = ex2(sf[nt][0] - mn0);
            float p01 = ex2(sf[nt][1] - mn0);
            float p10 = ex2(sf[nt][2] - mn1);
            float p11 = ex2(sf[nt][3] - mn1);
            rs0 += p00 + p01;
            rs1 += p10 + p11;
            *(__half2*)(prow + nt * 8 + 2 * r) = __floats2half2_rn(p00, p01);
            *(__half2*)(prow + 8 * HS + nt * 8 + 2 * r) = __floats2half2_rn(p10, p11);
        }
        rs0 += __shfl_xor_sync(0xffffffffu, rs0, 1);
        rs0 += __shfl_xor_sync(0xffffffffu, rs0, 2);
        rs1 += __shfl_xor_sync(0xffffffffu, rs1, 1);
        rs1 += __shfl_xor_sync(0xffffffffu, rs1, 2);
        l0 = l0 * sc0 + rs0;
        l1 = l1 * sc1 + rs1;
#pragma unroll
        for (int nt = 0; nt < 8; nt++) {
            of[nt][0] *= sc0; of[nt][1] *= sc0;
            of[nt][2] *= sc1; of[nt][3] *= sc1;
        }
        __syncwarp();

        {
            const uint32_t* prw = (const uint32_t*)Ps + (w * 16 + q) * HSW;
            const uint32_t* Vw = (const uint32_t*)Vs;
#pragma unroll
            for (int kk = 0; kk < 4; kk++) {
                uint32_t af[4];
                af[0] = prw[kk * 8 + r];
                af[1] = prw[8 * HSW + kk * 8 + r];
                af[2] = prw[kk * 8 + 4 + r];
                af[3] = prw[8 * HSW + kk * 8 + 4 + r];
#pragma unroll
                for (int nt = 0; nt < 8; nt++) {
                    uint32_t bfr[2];
                    const uint32_t* vp = Vw + (nt * 8 + q) * HSW + kk * 8 + r;
                    bfr[0] = vp[0];
                    bfr[1] = vp[4];
                    mma_f16(of[nt], af, bfr, of[nt]);
                }
            }
        }
    }

    const float il0 = 1.f / l0;
    const float il1 = 1.f / l1;
    __half* ob = attn + ((size_t)b * SS + bx * 64 + w * 16) * (HH * HDIM) + h * HDIM;
#pragma unroll
    for (int nt = 0; nt < 8; nt++) {
        int col = nt * 8 + 2 * r;
        *(__half2*)(ob + (size_t)q * (HH * HDIM) + col) =
            __floats2half2_rn(of[nt][0] * il0, of[nt][1] * il0);
        *(__half2*)(ob + (size_t)(q + 8) * (HH * HDIM) + col) =
            __floats2half2_rn(of[nt][2] * il1, of[nt][3] * il1);
    }
}

// ---------------------------------------------------------------------------
// Launch
// ---------------------------------------------------------------------------
extern "C" void kernel_launch(void* const* d_in, const int* in_sizes, int n_in,
                              void* d_out, int out_size)
{
    (void)in_sizes; (void)n_in; (void)out_size;
    const float* x    = (const float*)d_in[0];
    const float* cosT = (const float*)d_in[1];
    const float* sinT = (const float*)d_in[2];
    const float* Wq   = (const float*)d_in[3];
    const float* Wk   = (const float*)d_in[4];
    const float* Wv   = (const float*)d_in[5];
    const float* Wo   = (const float*)d_in[6];
    float* out = (float*)d_out;

    static bool attr_set = false;
    if (!attr_set) {
        cudaFuncSetAttribute(gemm_qkv_kernel,
                             cudaFuncAttributeMaxDynamicSharedMemorySize, XGSMEM);
        cudaFuncSetAttribute(gemm_o_kernel,
                             cudaFuncAttributeMaxDynamicSharedMemorySize, XGSMEM);
        attr_set = true;
    }

    __half *qt, *kt, *vh, *vtT, *attn, *xh, *wqt, *wkt, *wvt, *wot;
    cudaGetSymbolAddress((void**)&qt,   g_qt);
    cudaGetSymbolAddress((void**)&kt,   g_kt);
    cudaGetSymbolAddress((void**)&vh,   g_vh);
    cudaGetSymbolAddress((void**)&vtT,  g_vtT);
    cudaGetSymbolAddress((void**)&attn, g_attn);
    cudaGetSymbolAddress((void**)&xh,   g_xh);
    cudaGetSymbolAddress((void**)&wqt,  g_wqt);
    cudaGetSymbolAddress((void**)&wkt,  g_wkt);
    cudaGetSymbolAddress((void**)&wvt,  g_wvt);
    cudaGetSymbolAddress((void**)&wot,  g_wot);

    const int M = BB * SS;   // 4096

    // 0) Merged prep (x conversion + 4 weight transposes in one launch)
    prep_all_kernel<<<2560 + M * DD / 1024, 256>>>(
        x, Wq, Wk, Wv, Wo, xh, wqt, wkt, wvt, wot);

    // 1) Fused QKV projections + RoPE epilogue (3-stage pipelined GEMM)
    gemm_qkv_kernel<<<dim3(12, M / 128), 128, XGSMEM>>>(
        xh, wqt, wkt, wvt, cosT, sinT, qt, kt, vh);

    // 2) V transpose
    vtrans_kernel<<<dim3(SS / 32, 2 * BB * KVH), dim3(32, 8)>>>(vh, vtT);

    // 3) Causal GQA attention (R11 flash: 64q/CTA)
    flash_mma_kernel<<<dim3(SS / 64, BB * HH), 128>>>(qt, kt, vtT, attn);

    // 4) Output projection (3-stage pipelined GEMM)
    gemm_o_kernel<<<dim3(DD / 128, M / 128), 128, XGSMEM>>>(attn, wot, out);
}

// round 17
// speedup vs baseline: 1.1180x; 1.1180x over previous
#include <cuda_runtime.h>
#include <cuda_fp16.h>
#include <math.h>
#include <stdint.h>

// Problem constants
#define BB 2
#define SS 2048
#define DD 1024
#define HH 16
#define KVH 4
#define HDIM 64
#define NREP (HH / KVH)   // 4

// Scratch (allocation-free: __device__ globals)
__device__ __half g_qt[BB * HH * SS * HDIM];    // roped Q fp16, FSC folded
__device__ __half g_kt[BB * KVH * SS * HDIM];   // roped K fp16
__device__ __half g_vh[BB * SS * KVH * HDIM];   // V fp16 (b,s,kv,d)
__device__ __half g_vtT[BB * KVH * HDIM * SS];  // V^T fp16: [b][kv][d][s]
__device__ __half g_attn[BB * SS * HH * HDIM];  // attention out, fp16
__device__ __half g_xh[BB * SS * DD];           // x fp16 [M][K]
__device__ __half g_wqt[DD * DD];               // Wq^T fp16 [N][K]
__device__ __half g_wkt[256 * DD];
__device__ __half g_wvt[256 * DD];
__device__ __half g_wot[DD * DD];

#define FSC 0.18033688011112042f   // 0.125 * log2(e)

__device__ __forceinline__ float ex2(float x) {
    float y;
    asm("ex2.approx.ftz.f32 %0, %1;" : "=f"(y) : "f"(x));
    return y;
}
// pack two floats into fp16x2 bits (lo = a, hi = b), rne — same as __floats2half2_rn
__device__ __forceinline__ uint32_t packh2(float a, float b) {
    uint32_t u;
    asm("cvt.rn.f16x2.f32 %0, %1, %2;" : "=r"(u) : "f"(b), "f"(a));
    return u;
}
__device__ __forceinline__ void mma_f16(float d[4], const uint32_t a[4],
                                        const uint32_t b[2], const float c[4]) {
    asm volatile(
        "mma.sync.aligned.m16n8k16.row.col.f32.f16.f16.f32 "
        "{%0,%1,%2,%3}, {%4,%5,%6,%7}, {%8,%9}, {%10,%11,%12,%13};"
        : "=f"(d[0]), "=f"(d[1]), "=f"(d[2]), "=f"(d[3])
        : "r"(a[0]), "r"(a[1]), "r"(a[2]), "r"(a[3]),
          "r"(b[0]), "r"(b[1]),
          "f"(c[0]), "f"(c[1]), "f"(c[2]), "f"(c[3]));
}
__device__ __forceinline__ void ldsm_x4(uint32_t& r0, uint32_t& r1,
                                        uint32_t& r2, uint32_t& r3, uint32_t addr) {
    asm volatile("ldmatrix.sync.aligned.m8n8.x4.shared.b16 {%0,%1,%2,%3}, [%4];"
                 : "=r"(r0), "=r"(r1), "=r"(r2), "=r"(r3) : "r"(addr));
}
__device__ __forceinline__ void cpa16(uint32_t dst, const void* src) {
    asm volatile("cp.async.ca.shared.global [%0], [%1], 16;"
                 :: "r"(dst), "l"(src));
}
__device__ __forceinline__ void cp_commit() {
    asm volatile("cp.async.commit_group;" ::: "memory");
}
template <int N>
__device__ __forceinline__ void cp_wait() {
    asm volatile("cp.async.wait_group %0;" :: "n"(N) : "memory");
}

// ---------------------------------------------------------------------------
// Merged prep: one launch converts x -> fp16 AND all four W -> fp16 [N][K].
// ---------------------------------------------------------------------------
__global__ void prep_all_kernel(const float* __restrict__ x,
                                const float* __restrict__ Wq,
                                const float* __restrict__ Wk,
                                const float* __restrict__ Wv,
                                const float* __restrict__ Wo,
                                __half* __restrict__ xh,
                                __half* __restrict__ wqt,
                                __half* __restrict__ wkt,
                                __half* __restrict__ wvt,
                                __half* __restrict__ wot)
{
    const int tid = threadIdx.x;
    int bid = blockIdx.x;
    if (bid >= 2560) {
        int i = (bid - 2560) * 256 + tid;
        float4 v = ((const float4*)x)[i];
        __half2* o = (__half2*)xh;
        o[2 * i]     = __floats2half2_rn(v.x, v.y);
        o[2 * i + 1] = __floats2half2_rn(v.z, v.w);
        return;
    }
    __shared__ float tile[32][33];
    const float* W;
    __half* Wt;
    int N, n_t, k_t;
    if (bid < 1024)      { W = Wq; Wt = wqt; N = 1024; n_t = bid & 31; k_t = bid >> 5; }
    else if (bid < 1280) { W = Wk; Wt = wkt; N = 256;  bid -= 1024; n_t = bid & 7; k_t = bid >> 3; }
    else if (bid < 1536) { W = Wv; Wt = wvt; N = 256;  bid -= 1280; n_t = bid & 7; k_t = bid >> 3; }
    else                 { W = Wo; Wt = wot; N = 1024; bid -= 1536; n_t = bid & 31; k_t = bid >> 5; }
    const int n0 = n_t * 32, k0 = k_t * 32;
    const int tx = tid & 31;
    const int ty0 = tid >> 5;
#pragma unroll
    for (int ty = ty0; ty < 32; ty += 8)
        tile[ty][tx] = W[(size_t)(k0 + ty) * N + n0 + tx];
    __syncthreads();
#pragma unroll
    for (int ty = ty0; ty < 32; ty += 8)
        Wt[(size_t)(n0 + ty) * DD + k0 + tx] = __float2half_rn(tile[tx][ty]);
}

// ---------------------------------------------------------------------------
// fp16 ldmatrix GEMM, 2-stage cp.async (R11 proven config, 64 KB smem)
// ---------------------------------------------------------------------------
#define XTILE_B 16384
#define XSTAGE_B (XTILE_B * 2)
#define XGSMEM (XSTAGE_B * 2)

__device__ __forceinline__ void xgemm_copy_tile(
    const __half* __restrict__ A, const __half* __restrict__ Bt,
    int K, int bm, int bn, int k0,
    uint32_t abase, uint32_t bbase, int tid)
{
#pragma unroll
    for (int i = 0; i < 8; i++) {
        int e = tid + i * 128;
        int row = e >> 3;
        int ch = e & 7;
        int sch = ch ^ (row & 7);
        cpa16(abase + row * 128 + sch * 16,
              A + (size_t)(bm + row) * K + k0 + ch * 8);
    }
#pragma unroll
    for (int i = 0; i < 8; i++) {
        int e = tid + i * 128;
        int row = e >> 3;
        int ch = e & 7;
        int sch = ch ^ (row & 7);
        cpa16(bbase + row * 128 + sch * 16,
              Bt + (size_t)(bn + row) * K + k0 + ch * 8);
    }
}

__device__ __forceinline__ void xgemm_compute_tile(
    uint32_t abase, uint32_t bbase, float acc[4][8][4],
    int warpM, int warpN, int lane)
{
    const int lrow = lane & 15;
    const int lhi = lane >> 4;
#pragma unroll
    for (int ki = 0; ki < 4; ki++) {
        uint32_t av[4][4];
        uint32_t bv[4][4];
#pragma unroll
        for (int mi = 0; mi < 4; mi++) {
            int row = warpM + mi * 16 + lrow;
            int ch = (ki * 2 + lhi) ^ (row & 7);
            ldsm_x4(av[mi][0], av[mi][1], av[mi][2], av[mi][3],
                    abase + row * 128 + ch * 16);
        }
#pragma unroll
        for (int nj = 0; nj < 4; nj++) {
            int row = warpN + nj * 16 + lrow;
            int ch = (ki * 2 + lhi) ^ (row & 7);
            ldsm_x4(bv[nj][0], bv[nj][1], bv[nj][2], bv[nj][3],
                    bbase + row * 128 + ch * 16);
        }
#pragma unroll
        for (int mi = 0; mi < 4; mi++)
#pragma unroll
            for (int nt = 0; nt < 8; nt++) {
                uint32_t b[2];
                b[0] = bv[nt >> 1][nt & 1];
                b[1] = bv[nt >> 1][2 + (nt & 1)];
                mma_f16(acc[mi][nt], av[mi], b, acc[mi][nt]);
            }
    }
}

__device__ __forceinline__ void xgemm_mainloop(
    const __half* __restrict__ A, const __half* __restrict__ Bt,
    int K, int bm, int bn, float acc[4][8][4],
    int warpM, int warpN, int tid, int lane)
{
    extern __shared__ __align__(16) char xsm[];
    const uint32_t s0 = (uint32_t)__cvta_generic_to_shared(xsm);
    const uint32_t a0 = s0;
    const uint32_t b0 = s0 + XTILE_B;
    const uint32_t a1 = s0 + XSTAGE_B;
    const uint32_t b1 = s0 + XSTAGE_B + XTILE_B;

#pragma unroll
    for (int mi = 0; mi < 4; mi++)
#pragma unroll
        for (int nt = 0; nt < 8; nt++)
#pragma unroll
            for (int e = 0; e < 4; e++) acc[mi][nt][e] = 0.f;

    const int T = K / 64;

    xgemm_copy_tile(A, Bt, K, bm, bn, 0, a0, b0, tid);
    cp_commit();

    for (int t = 0; t < T - 1; t++) {
        uint32_t na = (t & 1) ? a0 : a1;
        uint32_t nb = (t & 1) ? b0 : b1;
        uint32_t la = (t & 1) ? a1 : a0;
        uint32_t lb = (t & 1) ? b1 : b0;
        xgemm_copy_tile(A, Bt, K, bm, bn, (t + 1) * 64, na, nb, tid);
        cp_commit();
        cp_wait<1>();
        __syncthreads();
        xgemm_compute_tile(la, lb, acc, warpM, warpN, lane);
        __syncthreads();
    }
    cp_wait<0>();
    __syncthreads();
    {
        uint32_t la = ((T - 1) & 1) ? a1 : a0;
        uint32_t lb = ((T - 1) & 1) ? b1 : b0;
        xgemm_compute_tile(la, lb, acc, warpM, warpN, lane);
    }
}

// ---------------------------------------------------------------------------
// Fused QKV projection with RoPE epilogue
// ---------------------------------------------------------------------------
__global__ __launch_bounds__(128)
void gemm_qkv_kernel(const __half* __restrict__ xh,
                     const __half* __restrict__ Wqt,
                     const __half* __restrict__ Wkt,
                     const __half* __restrict__ Wvt,
                     const float* __restrict__ cosT,
                     const float* __restrict__ sinT,
                     __half* __restrict__ qt,
                     __half* __restrict__ kt,
                     __half* __restrict__ vh)
{
    const int tid = threadIdx.x;
    const int lane = tid & 31;
    const int warp = tid >> 5;
    const int q = lane >> 2;
    const int r = lane & 3;
    const int warpM = (warp >> 1) * 64;
    const int warpN = (warp & 1) * 64;

    const int bx = blockIdx.x;
    const int bm = blockIdx.y * 128;

    const __half* Bt;
    int bn;
    if (bx < 8)       { Bt = Wqt; bn = bx * 128; }
    else if (bx < 10) { Bt = Wkt; bn = (bx - 8) * 128; }
    else              { Bt = Wvt; bn = (bx - 10) * 128; }

    float acc[4][8][4];
    xgemm_mainloop(xh, Bt, DD, bm, bn, acc, warpM, warpN, tid, lane);

    if (bx < 10) {
        const bool isQ = (bx < 8);
        const int head = (bn + warpN) >> 6;
        const float fs = isQ ? FSC : 1.0f;
#pragma unroll
        for (int mi = 0; mi < 4; mi++) {
            int rg0 = bm + warpM + mi * 16 + q;
#pragma unroll
            for (int hv = 0; hv < 2; hv++) {
                int rg = rg0 + hv * 8;
                int bb = rg >> 11;
                int s = rg & 2047;
                const float* crow = cosT + s * HDIM;
                const float* srow = sinT + s * HDIM;
                __half* orow;
                if (isQ)
                    orow = qt + (((size_t)(bb * HH + head) * SS + s) << 6);
                else
                    orow = kt + (((size_t)(bb * KVH + head) * SS + s) << 6);
#pragma unroll
                for (int nt = 0; nt < 4; nt++) {
                    int d = nt * 8 + 2 * r;
                    float2 cl = *(const float2*)(crow + d);
                    float2 sl = *(const float2*)(srow + d);
                    float2 chg = *(const float2*)(crow + d + 32);
                    float2 shg = *(const float2*)(srow + d + 32);
                    float v0 = acc[mi][nt][2 * hv];
                    float v1 = acc[mi][nt][2 * hv + 1];
                    float w0 = acc[mi][nt + 4][2 * hv];
                    float w1 = acc[mi][nt + 4][2 * hv + 1];
                    float lo0 = (v0 * cl.x - w0 * sl.x) * fs;
                    float lo1 = (v1 * cl.y - w1 * sl.y) * fs;
                    float hi0 = (w0 * chg.x + v0 * shg.x) * fs;
                    float hi1 = (w1 * chg.y + v1 * shg.y) * fs;
                    *(__half2*)(orow + d) = __floats2half2_rn(lo0, lo1);
                    *(__half2*)(orow + d + 32) = __floats2half2_rn(hi0, hi1);
                }
            }
        }
    } else {
#pragma unroll
        for (int mi = 0; mi < 4; mi++) {
            int rg0 = bm + warpM + mi * 16 + q;
#pragma unroll
            for (int nt = 0; nt < 8; nt++) {
                int col = bn + warpN + nt * 8 + 2 * r;
                *(__half2*)(vh + (size_t)rg0 * 256 + col) =
                    __floats2half2_rn(acc[mi][nt][0], acc[mi][nt][1]);
                *(__half2*)(vh + (size_t)(rg0 + 8) * 256 + col) =
                    __floats2half2_rn(acc[mi][nt][2], acc[mi][nt][3]);
            }
        }
    }
}

__global__ __launch_bounds__(128)
void gemm_o_kernel(const __half* __restrict__ A, const __half* __restrict__ Bt,
                   float* __restrict__ C)
{
    const int tid = threadIdx.x;
    const int lane = tid & 31;
    const int warp = tid >> 5;
    const int q = lane >> 2;
    const int r = lane & 3;
    const int warpM = (warp >> 1) * 64;
    const int warpN = (warp & 1) * 64;
    const int bm = blockIdx.y * 128;
    const int bn = blockIdx.x * 128;

    float acc[4][8][4];
    xgemm_mainloop(A, Bt, DD, bm, bn, acc, warpM, warpN, tid, lane);

#pragma unroll
    for (int mi = 0; mi < 4; mi++) {
        int row0 = bm + warpM + mi * 16 + q;
#pragma unroll
        for (int nt = 0; nt < 8; nt++) {
            int col = bn + warpN + nt * 8 + 2 * r;
            *(float2*)(C + (size_t)row0 * DD + col) =
                make_float2(acc[mi][nt][0], acc[mi][nt][1]);
            *(float2*)(C + (size_t)(row0 + 8) * DD + col) =
                make_float2(acc[mi][nt][2], acc[mi][nt][3]);
        }
    }
}

// ---------------------------------------------------------------------------
// V transpose: vh (b,s,kv,d) fp16 -> vtT (b,kv,d,s) fp16
// ---------------------------------------------------------------------------
__global__ void vtrans_kernel(const __half* __restrict__ vh,
                              __half* __restrict__ vtT)
{
    __shared__ __half tile[32][33];
    const int s0 = blockIdx.x * 32;
    const int d0 = (blockIdx.y & 1) * 32;
    const int bkv = blockIdx.y >> 1;
    const int b = bkv >> 2;
    const int kv = bkv & 3;
    const int tx = threadIdx.x;
#pragma unroll
    for (int ty = threadIdx.y; ty < 32; ty += 8)
        tile[ty][tx] = vh[(((size_t)(b * SS + s0 + ty)) * KVH + kv) * HDIM + d0 + tx];
    __syncthreads();
#pragma unroll
    for (int ty = threadIdx.y; ty < 32; ty += 8)
        vtT[((size_t)bkv * HDIM + d0 + ty) * SS + s0 + tx] = tile[tx][ty];
}

// ---------------------------------------------------------------------------
// fp16 MMA flash attention v4: 64q/CTA, P kept ENTIRELY in registers
// (QK accumulator fragment == PV A-fragment layout). No Ps smem, no
// __syncwarp, smem = K + V only (18.4 KB). __launch_bounds__(128,4).
// ---------------------------------------------------------------------------
#define HS 72
#define HSW 36

__global__ __launch_bounds__(128, 4)
void flash_mma_kernel(const __half* __restrict__ Qt, const __half* __restrict__ Kt,
                      const __half* __restrict__ VtT, __half* __restrict__ attn)
{
    __shared__ __align__(16) __half Ks[64 * HS];
    __shared__ __align__(16) __half Vs[64 * HS];

    const int tid = threadIdx.x;
    const int lane = tid & 31;
    const int w = tid >> 5;
    const int q = lane >> 2;
    const int r = lane & 3;

    const int bx = gridDim.x - 1 - blockIdx.x;
    const int bh = blockIdx.y;
    const int b = bh >> 4;
    const int h = bh & 15;
    const int kvh = h >> 2;

    const __half* qbase = Qt + ((size_t)bh * SS + bx * 64) * HDIM;
    const __half* kbase = Kt + (size_t)(b * KVH + kvh) * SS * HDIM;
    const __half* vbase = VtT + (size_t)(b * KVH + kvh) * HDIM * SS;

    // Stage Q through Ks, read fragments, then Ks becomes the K buffer
#pragma unroll
    for (int it = 0; it < 4; it++) {
        int e = tid + it * 128;
        int row = e >> 3;
        int ch = e & 7;
        *(uint4*)(Ks + row * HS + ch * 8) =
            *(const uint4*)(qbase + row * HDIM + ch * 8);
    }
    __syncthreads();

    uint32_t qf[4][4];
    {
        const uint32_t* Pw = (const uint32_t*)Ks;
#pragma unroll
        for (int ki = 0; ki < 4; ki++) {
            const uint32_t* p = Pw + (w * 16 + q) * HSW + ki * 8 + r;
            qf[ki][0] = p[0];
            qf[ki][1] = p[8 * HSW];
            qf[ki][2] = p[4];
            qf[ki][3] = p[8 * HSW + 4];
        }
    }

    float of[8][4];
#pragma unroll
    for (int nt = 0; nt < 8; nt++)
#pragma unroll
        for (int e = 0; e < 4; e++) of[nt][e] = 0.f;
    float m0 = -INFINITY, m1 = -INFINITY, l0 = 0.f, l1 = 0.f;

    for (int jt = 0; jt <= bx; jt++) {
        __syncthreads();   // prior tile reads done (also covers Q staging reads)
#pragma unroll
        for (int it = 0; it < 4; it++) {
            int e = tid + it * 128;
            int row = e >> 3;
            int ch = e & 7;
            *(uint4*)(Ks + row * HS + ch * 8) =
                *(const uint4*)(kbase + (size_t)(jt * 64 + row) * HDIM + ch * 8);
            *(uint4*)(Vs + row * HS + ch * 8) =
                *(const uint4*)(vbase + (size_t)row * SS + jt * 64 + ch * 8);
        }
        __syncthreads();

        // S = Q @ K^T
        float sf[8][4];
#pragma unroll
        for (int nt = 0; nt < 8; nt++)
#pragma unroll
            for (int e = 0; e < 4; e++) sf[nt][e] = 0.f;
        {
            const uint32_t* Kw = (const uint32_t*)Ks;
#pragma unroll
            for (int ki = 0; ki < 4; ki++) {
#pragma unroll
                for (int nt = 0; nt < 8; nt++) {
                    uint32_t bfr[2];
                    const uint32_t* kp = Kw + (nt * 8 + q) * HSW + ki * 8 + r;
                    bfr[0] = kp[0];
                    bfr[1] = kp[4];
                    mma_f16(sf[nt], qf[ki], bfr, sf[nt]);
                }
            }
        }

        if (jt == bx) {
            const int rowA = w * 16 + q;
            const int rowB = rowA + 8;
#pragma unroll
            for (int nt = 0; nt < 8; nt++) {
                int col = nt * 8 + 2 * r;
                if (col     > rowA) sf[nt][0] = -1e30f;
                if (col + 1 > rowA) sf[nt][1] = -1e30f;
                if (col     > rowB) sf[nt][2] = -1e30f;
                if (col + 1 > rowB) sf[nt][3] = -1e30f;
            }
        }

        // Online softmax (rows q, q+8)
        float mxA = -1e30f, mxB = -1e30f;
#pragma unroll
        for (int nt = 0; nt < 8; nt++) {
            mxA = fmaxf(mxA, fmaxf(sf[nt][0], sf[nt][1]));
            mxB = fmaxf(mxB, fmaxf(sf[nt][2], sf[nt][3]));
        }
        mxA = fmaxf(mxA, __shfl_xor_sync(0xffffffffu, mxA, 1));
        mxA = fmaxf(mxA, __shfl_xor_sync(0xffffffffu, mxA, 2));
        mxB = fmaxf(mxB, __shfl_xor_sync(0xffffffffu, mxB, 1));
        mxB = fmaxf(mxB, __shfl_xor_sync(0xffffffffu, mxB, 2));

        float mn0 = fmaxf(m0, mxA);
        float mn1 = fmaxf(m1, mxB);
        float sc0 = ex2(m0 - mn0);
        float sc1 = ex2(m1 - mn1);
        m0 = mn0; m1 = mn1;

        // P in registers: ph0[nt] = rows q (keys nt*8+2r, +1); ph1[nt] = rows q+8
        uint32_t ph0[8], ph1[8];
        float rs0 = 0.f, rs1 = 0.f;
#pragma unroll
        for (int nt = 0; nt < 8; nt++) {
            float p00 = ex2(sf[nt][0] - mn0);
            float p01 = ex2(sf[nt][1] - mn0);
            float p10 = ex2(sf[nt][2] - mn1);
            float p11 = ex2(sf[nt][3] - mn1);
            rs0 += p00 + p01;
            rs1 += p10 + p11;
            ph0[nt] = packh2(p00, p01);
            ph1[nt] = packh2(p10, p11);
        }
        rs0 += __shfl_xor_sync(0xffffffffu, rs0, 1);
        rs0 += __shfl_xor_sync(0xffffffffu, rs0, 2);
        rs1 += __shfl_xor_sync(0xffffffffu, rs1, 1);
        rs1 += __shfl_xor_sync(0xffffffffu, rs1, 2);
        l0 = l0 * sc0 + rs0;
        l1 = l1 * sc1 + rs1;
#pragma unroll
        for (int nt = 0; nt < 8; nt++) {
            of[nt][0] *= sc0; of[nt][1] *= sc0;
            of[nt][2] *= sc1; of[nt][3] *= sc1;
        }

        // O += P @ V   (A-fragment directly from registers)
        {
            const uint32_t* Vw = (const uint32_t*)Vs;
#pragma unroll
            for (int kk = 0; kk < 4; kk++) {
                uint32_t af[4];
                af[0] = ph0[2 * kk];
                af[1] = ph1[2 * kk];
                af[2] = ph0[2 * kk + 1];
                af[3] = ph1[2 * kk + 1];
#pragma unroll
                for (int nt = 0; nt < 8; nt++) {
                    uint32_t bfr[2];
                    const uint32_t* vp = Vw + (nt * 8 + q) * HSW + kk * 8 + r;
                    bfr[0] = vp[0];
                    bfr[1] = vp[4];
                    mma_f16(of[nt], af, bfr, of[nt]);
                }
            }
        }
    }

    const float il0 = 1.f / l0;
    const float il1 = 1.f / l1;
    __half* ob = attn + ((size_t)b * SS + bx * 64 + w * 16) * (HH * HDIM) + h * HDIM;
#pragma unroll
    for (int nt = 0; nt < 8; nt++) {
        int col = nt * 8 + 2 * r;
        *(__half2*)(ob + (size_t)q * (HH * HDIM) + col) =
            __floats2half2_rn(of[nt][0] * il0, of[nt][1] * il0);
        *(__half2*)(ob + (size_t)(q + 8) * (HH * HDIM) + col) =
            __floats2half2_rn(of[nt][2] * il1, of[nt][3] * il1);
    }
}

// ---------------------------------------------------------------------------
// Launch
// ---------------------------------------------------------------------------
extern "C" void kernel_launch(void* const* d_in, const int* in_sizes, int n_in,
                              void* d_out, int out_size)
{
    (void)in_sizes; (void)n_in; (void)out_size;
    const float* x    = (const float*)d_in[0];
    const float* cosT = (const float*)d_in[1];
    const float* sinT = (const float*)d_in[2];
    const float* Wq   = (const float*)d_in[3];
    const float* Wk   = (const float*)d_in[4];
    const float* Wv   = (const float*)d_in[5];
    const float* Wo   = (const float*)d_in[6];
    float* out = (float*)d_out;

    static bool attr_set = false;
    if (!attr_set) {
        cudaFuncSetAttribute(gemm_qkv_kernel,
                             cudaFuncAttributeMaxDynamicSharedMemorySize, XGSMEM);
        cudaFuncSetAttribute(gemm_o_kernel,
                             cudaFuncAttributeMaxDynamicSharedMemorySize, XGSMEM);
        attr_set = true;
    }

    __half *qt, *kt, *vh, *vtT, *attn, *xh, *wqt, *wkt, *wvt, *wot;
    cudaGetSymbolAddress((void**)&qt,   g_qt);
    cudaGetSymbolAddress((void**)&kt,   g_kt);
    cudaGetSymbolAddress((void**)&vh,   g_vh);
    cudaGetSymbolAddress((void**)&vtT,  g_vtT);
    cudaGetSymbolAddress((void**)&attn, g_attn);
    cudaGetSymbolAddress((void**)&xh,   g_xh);
    cudaGetSymbolAddress((void**)&wqt,  g_wqt);
    cudaGetSymbolAddress((void**)&wkt,  g_wkt);
    cudaGetSymbolAddress((void**)&wvt,  g_wvt);
    cudaGetSymbolAddress((void**)&wot,  g_wot);

    const int M = BB * SS;   // 4096

    // 0) Merged prep
    prep_all_kernel<<<2560 + M * DD / 1024, 256>>>(
        x, Wq, Wk, Wv, Wo, xh, wqt, wkt, wvt, wot);

    // 1) Fused QKV projections + RoPE epilogue (2-stage pipelined GEMM)
    gemm_qkv_kernel<<<dim3(12, M / 128), 128, XGSMEM>>>(
        xh, wqt, wkt, wvt, cosT, sinT, qt, kt, vh);

    // 2) V transpose
    vtrans_kernel<<<dim3(SS / 32, 2 * BB * KVH), dim3(32, 8)>>>(vh, vtT);

    // 3) Causal GQA attention (flash v4: register-resident P)
    flash_mma_kernel<<<dim3(SS / 64, BB * HH), 128>>>(qt, kt, vtT, attn);

    // 4) Output projection
    gemm_o_kernel<<<dim3(DD / 128, M / 128), 128, XGSMEM>>>(attn, wot, out);
}